// round 5
// baseline (speedup 1.0000x reference)
#include <cuda_runtime.h>

// Problem shape (fixed by the dataset)
#define BB 16
#define NN 8192
#define FF 256
#define ROW4 64            // float4s per row (FF/4)
#define TOTAL4 (BB * NN * ROW4)   // 8,388,608 float4s
#define EPS 1e-3f

// Scratch (allocation-free rule: __device__ globals)
__device__ float g_sum[FF];
__device__ float g_sumsq[FF];
__device__ float g_scale[FF];
__device__ float g_shift[FF];

// ---------------- kernel 0: zero accumulators ----------------
__global__ void mbn_zero_kernel() {
    int t = threadIdx.x;          // 256 threads
    g_sum[t]   = 0.0f;
    g_sumsq[t] = 0.0f;
}

// ---------------- kernel 1: masked sum / sumsq ----------------
// Each thread owns feature group fg = tid % 64 (features 4*fg .. 4*fg+3),
// guaranteed stable because grid stride is a multiple of 64 float4s.
__global__ void mbn_stats_kernel(const float4* __restrict__ x,
                                 const int* __restrict__ nv) {
    __shared__ int s_nv[BB];
    if (threadIdx.x < BB) s_nv[threadIdx.x] = nv[threadIdx.x];
    __syncthreads();

    float s0 = 0.f, s1 = 0.f, s2 = 0.f, s3 = 0.f;
    float q0 = 0.f, q1 = 0.f, q2 = 0.f, q3 = 0.f;

    int idx    = blockIdx.x * blockDim.x + threadIdx.x;
    int stride = gridDim.x * blockDim.x;      // multiple of 256 -> multiple of 64
    for (; idx < TOTAL4; idx += stride) {
        int row = idx >> 6;                   // / ROW4
        int n   = row & (NN - 1);
        int b   = row >> 13;                  // / NN
        if (n < s_nv[b]) {
            float4 v = x[idx];
            s0 += v.x; s1 += v.y; s2 += v.z; s3 += v.w;
            q0 += v.x * v.x; q1 += v.y * v.y;
            q2 += v.z * v.z; q3 += v.w * v.w;
        }
    }

    // Block reduction: threads {t, t+64, t+128, t+192} share a feature group.
    __shared__ float red[256 * 4];
    int tid = threadIdx.x;
    red[tid * 4 + 0] = s0; red[tid * 4 + 1] = s1;
    red[tid * 4 + 2] = s2; red[tid * 4 + 3] = s3;
    __syncthreads();
    if (tid < 64) {
        #pragma unroll
        for (int j = 0; j < 4; j++) {
            float t = red[tid * 4 + j] + red[(tid + 64) * 4 + j] +
                      red[(tid + 128) * 4 + j] + red[(tid + 192) * 4 + j];
            atomicAdd(&g_sum[tid * 4 + j], t);
        }
    }
    __syncthreads();
    red[tid * 4 + 0] = q0; red[tid * 4 + 1] = q1;
    red[tid * 4 + 2] = q2; red[tid * 4 + 3] = q3;
    __syncthreads();
    if (tid < 64) {
        #pragma unroll
        for (int j = 0; j < 4; j++) {
            float t = red[tid * 4 + j] + red[(tid + 64) * 4 + j] +
                      red[(tid + 128) * 4 + j] + red[(tid + 192) * 4 + j];
            atomicAdd(&g_sumsq[tid * 4 + j], t);
        }
    }
}

// ---------------- kernel 2: finalize scale/shift ----------------
__global__ void mbn_finalize_kernel(const int* __restrict__ nv,
                                    const float* __restrict__ gamma,
                                    const float* __restrict__ beta) {
    __shared__ float s_cnt;
    if (threadIdx.x == 0) {
        int c = 0;
        #pragma unroll
        for (int i = 0; i < BB; i++) c += nv[i];
        s_cnt = fmaxf((float)c, 1.0f);
    }
    __syncthreads();
    int f = threadIdx.x;                      // 256 threads
    float cnt  = s_cnt;
    float mean = g_sum[f] / cnt;
    float var  = g_sumsq[f] / cnt - mean * mean;
    float inv  = rsqrtf(var + EPS);
    float sc   = inv * gamma[f];
    g_scale[f] = sc;
    g_shift[f] = beta[f] - mean * sc;
}

// ---------------- kernel 3: normalize + zero padding ----------------
__global__ void mbn_norm_kernel(const float4* __restrict__ x,
                                const int* __restrict__ nv,
                                float4* __restrict__ out) {
    __shared__ int s_nv[BB];
    if (threadIdx.x < BB) s_nv[threadIdx.x] = nv[threadIdx.x];
    __syncthreads();

    // Register-resident scale/shift: this thread only ever touches 4 features.
    int fg = (threadIdx.x & 63) * 4;
    float sc0 = g_scale[fg + 0], sc1 = g_scale[fg + 1];
    float sc2 = g_scale[fg + 2], sc3 = g_scale[fg + 3];
    float sh0 = g_shift[fg + 0], sh1 = g_shift[fg + 1];
    float sh2 = g_shift[fg + 2], sh3 = g_shift[fg + 3];

    int idx    = blockIdx.x * blockDim.x + threadIdx.x;
    int stride = gridDim.x * blockDim.x;
    for (; idx < TOTAL4; idx += stride) {
        int row = idx >> 6;
        int n   = row & (NN - 1);
        int b   = row >> 13;
        float4 o;
        if (n < s_nv[b]) {
            float4 v = x[idx];
            o.x = fmaf(v.x, sc0, sh0);
            o.y = fmaf(v.y, sc1, sh1);
            o.z = fmaf(v.z, sc2, sh2);
            o.w = fmaf(v.w, sc3, sh3);
        } else {
            o.x = 0.f; o.y = 0.f; o.z = 0.f; o.w = 0.f;
        }
        out[idx] = o;
    }
}

extern "C" void kernel_launch(void* const* d_in, const int* in_sizes, int n_in,
                              void* d_out, int out_size) {
    const float4* x     = (const float4*)d_in[0];   // voxel_features [16,8192,256]
    const int*    nv    = (const int*)d_in[1];      // num_valid_voxels [16]
    const float*  gamma = (const float*)d_in[2];    // [256]
    const float*  beta  = (const float*)d_in[3];    // [256]
    float4*       out   = (float4*)d_out;

    const int threads = 256;
    const int grid_big = 148 * 4;   // grid-stride; stride stays a multiple of 64

    mbn_zero_kernel<<<1, threads>>>();
    mbn_stats_kernel<<<grid_big, threads>>>(x, nv);
    mbn_finalize_kernel<<<1, threads>>>(nv, gamma, beta);
    mbn_norm_kernel<<<grid_big * 2, threads>>>(x, nv, out);
}